// round 1
// baseline (speedup 1.0000x reference)
#include <cuda_runtime.h>
#include <math.h>

#define S_LEN   4096
#define HEAD_D  64
#define WIN     256
#define QT      64
#define KT      64
#define NT      9          // key tiles per query tile: offsets -256..+256 step 64
#define STR     68         // padded smem row stride (floats); 68*4B = 272B = 17*16B
#define NTHREADS 256

__global__ __launch_bounds__(NTHREADS, 2)
void swa_fp32_kernel(const float* __restrict__ Qg,
                     const float* __restrict__ Kg,
                     const float* __restrict__ Vg,
                     float* __restrict__ Og) {
    extern __shared__ float smem[];
    float* Qs = smem;                    // QT x STR
    float* Ks = Qs + QT * STR;           // KT x STR
    float* Vs = Ks + KT * STR;           // KT x STR
    float* Ps = Vs + KT * STR;           // QT x STR

    const int tid = threadIdx.x;
    const int tx  = tid & 15;            // 0..15
    const int ty  = tid >> 4;            // 0..15
    const int q0  = blockIdx.x * QT;
    const int bh  = blockIdx.y;
    const size_t base = (size_t)bh * S_LEN * HEAD_D;

    // ---- load Q tile (coalesced float4) ----
    {
        const float4* Qv = (const float4*)(Qg + base + (size_t)q0 * HEAD_D);
        #pragma unroll
        for (int it = 0; it < 4; it++) {
            int r  = ty + 16 * it;
            float4 v = Qv[r * 16 + tx];
            *(float4*)&Qs[r * STR + tx * 4] = v;
        }
    }

    // accumulators: rows r = ty + 16*i, dims d = 4*tx + j
    float o[4][4];
    float m[4], l[4];
    #pragma unroll
    for (int i = 0; i < 4; i++) {
        m[i] = -INFINITY; l[i] = 0.f;
        #pragma unroll
        for (int j = 0; j < 4; j++) o[i][j] = 0.f;
    }

    const float scale = 0.125f;   // 1/sqrt(64)

    for (int t = 0; t < NT; t++) {
        const int k0 = q0 - WIN + t * KT;
        if (k0 <= -KT || k0 >= S_LEN) continue;   // uniform per block

        __syncthreads();   // prior iter's GEMM2 done before overwriting Ks/Vs

        // ---- load K,V tiles (zero-fill OOB rows) ----
        #pragma unroll
        for (int it = 0; it < 4; it++) {
            int r  = ty + 16 * it;
            int ki = k0 + r;
            float4 kv = make_float4(0.f, 0.f, 0.f, 0.f);
            float4 vv = make_float4(0.f, 0.f, 0.f, 0.f);
            if (ki >= 0 && ki < S_LEN) {
                kv = *(const float4*)(Kg + base + (size_t)ki * HEAD_D + tx * 4);
                vv = *(const float4*)(Vg + base + (size_t)ki * HEAD_D + tx * 4);
            }
            *(float4*)&Ks[r * STR + tx * 4] = kv;
            *(float4*)&Vs[r * STR + tx * 4] = vv;
        }
        __syncthreads();

        // ---- GEMM1: s[i][j] = Q[r] . K[c],  r = ty+16i, c = tx+16j ----
        float s[4][4];
        #pragma unroll
        for (int i = 0; i < 4; i++)
            #pragma unroll
            for (int j = 0; j < 4; j++) s[i][j] = 0.f;

        #pragma unroll 4
        for (int d4 = 0; d4 < 16; d4++) {
            float4 qv[4], kv[4];
            #pragma unroll
            for (int i = 0; i < 4; i++)
                qv[i] = *(const float4*)&Qs[(ty + 16 * i) * STR + d4 * 4];
            #pragma unroll
            for (int j = 0; j < 4; j++)
                kv[j] = *(const float4*)&Ks[(tx + 16 * j) * STR + d4 * 4];
            #pragma unroll
            for (int i = 0; i < 4; i++)
                #pragma unroll
                for (int j = 0; j < 4; j++) {
                    s[i][j] += qv[i].x * kv[j].x;
                    s[i][j] += qv[i].y * kv[j].y;
                    s[i][j] += qv[i].z * kv[j].z;
                    s[i][j] += qv[i].w * kv[j].w;
                }
        }

        // ---- scale + band mask ----
        // interior tiles (t=1..7, fully in-range) are provably unmasked:
        // diff = (k0-q0) + (c-r) in [-255,255] subset of [-256,256]
        const bool need_mask = (k0 < 0) || (k0 + KT > S_LEN) || (t == 0) || (t == NT - 1);
        #pragma unroll
        for (int i = 0; i < 4; i++) {
            const int qi = q0 + ty + 16 * i;
            #pragma unroll
            for (int j = 0; j < 4; j++) {
                float v = s[i][j] * scale;
                if (need_mask) {
                    const int ki = k0 + tx + 16 * j;
                    const int df = ki - qi;
                    const bool ok = (ki >= 0) && (ki < S_LEN) && (df >= -WIN) && (df <= WIN);
                    v = ok ? v : -INFINITY;
                }
                s[i][j] = v;
            }
        }

        // ---- online softmax (row groups = 16 lanes sharing ty) ----
        #pragma unroll
        for (int i = 0; i < 4; i++) {
            float tm = fmaxf(fmaxf(s[i][0], s[i][1]), fmaxf(s[i][2], s[i][3]));
            #pragma unroll
            for (int off = 8; off; off >>= 1)
                tm = fmaxf(tm, __shfl_xor_sync(0xffffffffu, tm, off));
            const float mn = fmaxf(m[i], tm);
            const float alpha = __expf(m[i] - mn);   // m=-inf, mn finite -> 0
            float rs = 0.f;
            #pragma unroll
            for (int j = 0; j < 4; j++) {
                const float p = __expf(s[i][j] - mn);  // masked -> exp(-inf)=0
                s[i][j] = p;
                rs += p;
            }
            #pragma unroll
            for (int off = 8; off; off >>= 1)
                rs += __shfl_xor_sync(0xffffffffu, rs, off);
            l[i] = l[i] * alpha + rs;
            m[i] = mn;
            #pragma unroll
            for (int j = 0; j < 4; j++) o[i][j] *= alpha;
        }

        // ---- stage P to smem ----
        #pragma unroll
        for (int i = 0; i < 4; i++)
            #pragma unroll
            for (int j = 0; j < 4; j++)
                Ps[(ty + 16 * i) * STR + tx + 16 * j] = s[i][j];
        __syncthreads();

        // ---- GEMM2: o[r][d] += P[r][k] * V[k][d],  d = 4*tx + j ----
        #pragma unroll 2
        for (int k4 = 0; k4 < 16; k4++) {
            float4 pv[4];
            #pragma unroll
            for (int i = 0; i < 4; i++)
                pv[i] = *(const float4*)&Ps[(ty + 16 * i) * STR + k4 * 4];
            float4 vv[4];
            #pragma unroll
            for (int kk = 0; kk < 4; kk++)
                vv[kk] = *(const float4*)&Vs[(k4 * 4 + kk) * STR + tx * 4];
            #pragma unroll
            for (int i = 0; i < 4; i++) {
                o[i][0] += pv[i].x * vv[0].x; o[i][0] += pv[i].y * vv[1].x;
                o[i][0] += pv[i].z * vv[2].x; o[i][0] += pv[i].w * vv[3].x;
                o[i][1] += pv[i].x * vv[0].y; o[i][1] += pv[i].y * vv[1].y;
                o[i][1] += pv[i].z * vv[2].y; o[i][1] += pv[i].w * vv[3].y;
                o[i][2] += pv[i].x * vv[0].z; o[i][2] += pv[i].y * vv[1].z;
                o[i][2] += pv[i].z * vv[2].z; o[i][2] += pv[i].w * vv[3].z;
                o[i][3] += pv[i].x * vv[0].w; o[i][3] += pv[i].y * vv[1].w;
                o[i][3] += pv[i].z * vv[2].w; o[i][3] += pv[i].w * vv[3].w;
            }
        }
    }

    // ---- epilogue: normalize + coalesced float4 store ----
    float4* Ov = (float4*)(Og + base + (size_t)q0 * HEAD_D);
    #pragma unroll
    for (int i = 0; i < 4; i++) {
        const float inv = 1.f / l[i];
        float4 v = make_float4(o[i][0] * inv, o[i][1] * inv,
                               o[i][2] * inv, o[i][3] * inv);
        Ov[(ty + 16 * i) * 16 + tx] = v;
    }
}

extern "C" void kernel_launch(void* const* d_in, const int* in_sizes, int n_in,
                              void* d_out, int out_size) {
    const float* Q = (const float*)d_in[0];
    const float* K = (const float*)d_in[1];
    const float* V = (const float*)d_in[2];
    float* O = (float*)d_out;

    const int BH = in_sizes[0] / (S_LEN * HEAD_D);   // B*H = 32
    const size_t smem_bytes = 4u * QT * STR * sizeof(float);   // 69632

    // idempotent, host-side only; safe under graph capture
    cudaFuncSetAttribute(swa_fp32_kernel,
                         cudaFuncAttributeMaxDynamicSharedMemorySize,
                         (int)smem_bytes);

    dim3 grid(S_LEN / QT, BH);
    swa_fp32_kernel<<<grid, NTHREADS, smem_bytes>>>(Q, K, V, O);
}

// round 4
// speedup vs baseline: 1.6513x; 1.6513x over previous
#include <cuda_runtime.h>
#include <cstdint>
#include <math.h>

#define S_LEN  4096
#define HD     64
#define QT     64
#define SCALE  0.125f

// smem word offsets (uint32 units)
#define QSTR 68
#define KSTR 68
#define VSTR 72
#define PSTR 68
#define Q_OFF 0
#define K_OFF (Q_OFF + 64 * QSTR)          // 4352
#define V_OFF (K_OFF + 64 * KSTR)          // 8704
#define P_OFF (V_OFF + 64 * VSTR)          // 13312
#define SMEM_WORDS (P_OFF + 64 * PSTR)     // 17664
#define SMEM_BYTES (SMEM_WORDS * 4)        // 70656

__device__ __forceinline__ uint32_t f2tf(float f) {
    uint32_t r;
    asm("cvt.rna.tf32.f32 %0, %1;" : "=r"(r) : "f"(f));
    return r;
}

__device__ __forceinline__ void mma8(float* d, const uint32_t* a,
                                     uint32_t b0, uint32_t b1) {
    asm volatile(
        "mma.sync.aligned.m16n8k8.row.col.f32.tf32.tf32.f32 "
        "{%0,%1,%2,%3}, {%4,%5,%6,%7}, {%8,%9}, {%0,%1,%2,%3};"
        : "+f"(d[0]), "+f"(d[1]), "+f"(d[2]), "+f"(d[3])
        : "r"(a[0]), "r"(a[1]), "r"(a[2]), "r"(a[3]), "r"(b0), "r"(b1));
}

// load a [64 x 64] f32 tile (row-major, stride 64) into smem (word stride str),
// tf32-rounded; 128 threads, each covers half a row as 8 float4.
__device__ __forceinline__ void ld_tile(uint32_t* sm, int base, int str,
                                        const float* g, int tid) {
    const int lr = tid >> 1;
    const int h  = tid & 1;
    const float4* src = (const float4*)g + lr * 16 + h * 8;
    uint32_t* dst = sm + base + lr * str + h * 32;
    #pragma unroll
    for (int j = 0; j < 8; j++) {
        float4 v = src[j];
        uint4 u = make_uint4(f2tf(v.x), f2tf(v.y), f2tf(v.z), f2tf(v.w));
        *(uint4*)(dst + 4 * j) = u;
    }
}

__global__ __launch_bounds__(128, 3)
void swa_mma_tf32(const float* __restrict__ Qg, const float* __restrict__ Kg,
                  const float* __restrict__ Vg, float* __restrict__ Og) {
    extern __shared__ uint32_t sm[];
    const int tid  = threadIdx.x;
    const int lane = tid & 31;
    const int wid  = tid >> 5;
    const int g    = lane & 3;        // thread-in-group (k / col2 index)
    const int r1   = lane >> 2;       // group id (row within m16 tile)
    const int bx   = blockIdx.x;
    const int q0   = bx * QT;
    const size_t base = (size_t)blockIdx.y * (S_LEN * HD);

    const int rl1 = wid * 16 + r1;    // local query rows owned by this thread
    const int rl2 = rl1 + 8;

    // ---- stage Q (tf32) ----
    ld_tile(sm, Q_OFF, QSTR, Qg + base + (size_t)q0 * HD, tid);
    __syncthreads();

    // ---- preload Q A-fragments for all 8 k-steps ----
    uint32_t qa[8][4];
    #pragma unroll
    for (int ks = 0; ks < 8; ks++) {
        const int cb = ks * 8 + g;
        qa[ks][0] = sm[Q_OFF + rl1 * QSTR + cb];
        qa[ks][1] = sm[Q_OFF + rl2 * QSTR + cb];
        qa[ks][2] = sm[Q_OFF + rl1 * QSTR + cb + 4];
        qa[ks][3] = sm[Q_OFF + rl2 * QSTR + cb + 4];
    }

    float o[8][4];
    #pragma unroll
    for (int nt = 0; nt < 8; nt++)
        #pragma unroll
        for (int j = 0; j < 4; j++) o[nt][j] = 0.f;
    float m1 = -INFINITY, m2 = -INFINITY, l1 = 0.f, l2 = 0.f;

    // valid key tiles: k0 = q0 - 256 + t*64, t in [t_start, t_end]
    const int t_start = (bx < 4)  ? (4 - bx)  : 0;
    const int t_end   = (bx > 59) ? (67 - bx) : 8;

    for (int t = t_start; t <= t_end; t++) {
        const int k0 = q0 - 256 + t * 64;

        __syncthreads();   // previous iteration's MMA2 reads of Ks/Vs done
        ld_tile(sm, K_OFF, KSTR, Kg + base + (size_t)k0 * HD, tid);
        ld_tile(sm, V_OFF, VSTR, Vg + base + (size_t)k0 * HD, tid);
        __syncthreads();

        // ---- MMA1: S = Q . K^T  (per warp: 16 q-rows x 64 keys) ----
        float s[8][4];
        #pragma unroll
        for (int nt = 0; nt < 8; nt++)
            #pragma unroll
            for (int j = 0; j < 4; j++) s[nt][j] = 0.f;

        #pragma unroll
        for (int ks = 0; ks < 8; ks++) {
            const int cb = ks * 8 + g;
            #pragma unroll
            for (int nt = 0; nt < 8; nt++) {
                const uint32_t b0 = sm[K_OFF + (nt * 8 + r1) * KSTR + cb];
                const uint32_t b1 = sm[K_OFF + (nt * 8 + r1) * KSTR + cb + 4];
                mma8(s[nt], qa[ks], b0, b1);
            }
        }

        // ---- scale + band mask + online softmax ----
        const bool mlo = (t == 0);   // need key >= query  (diff >= -256)
        const bool mhi = (t == 8);   // need key <= query  (diff <= +256)
        float mx1 = -INFINITY, mx2 = -INFINITY;
        #pragma unroll
        for (int nt = 0; nt < 8; nt++) {
            #pragma unroll
            for (int sl = 0; sl < 2; sl++) {
                const int c = nt * 8 + 2 * g + sl;
                float v1 = s[nt][sl] * SCALE;
                float v2 = s[nt][2 + sl] * SCALE;
                if (mlo) { if (c < rl1) v1 = -INFINITY; if (c < rl2) v2 = -INFINITY; }
                if (mhi) { if (c > rl1) v1 = -INFINITY; if (c > rl2) v2 = -INFINITY; }
                s[nt][sl] = v1;  s[nt][2 + sl] = v2;
                mx1 = fmaxf(mx1, v1);  mx2 = fmaxf(mx2, v2);
            }
        }
        mx1 = fmaxf(mx1, __shfl_xor_sync(0xffffffffu, mx1, 1));
        mx1 = fmaxf(mx1, __shfl_xor_sync(0xffffffffu, mx1, 2));
        mx2 = fmaxf(mx2, __shfl_xor_sync(0xffffffffu, mx2, 1));
        mx2 = fmaxf(mx2, __shfl_xor_sync(0xffffffffu, mx2, 2));

        const float mn1 = fmaxf(m1, mx1);
        const float mn2 = fmaxf(m2, mx2);
        const float a1 = __expf(m1 - mn1);
        const float a2 = __expf(m2 - mn2);
        m1 = mn1; m2 = mn2;

        float sum1 = 0.f, sum2 = 0.f;
        #pragma unroll
        for (int nt = 0; nt < 8; nt++) {
            const uint32_t p0 = f2tf(__expf(s[nt][0] - mn1));
            const uint32_t p1 = f2tf(__expf(s[nt][1] - mn1));
            const uint32_t p2 = f2tf(__expf(s[nt][2] - mn2));
            const uint32_t p3 = f2tf(__expf(s[nt][3] - mn2));
            sum1 += __uint_as_float(p0) + __uint_as_float(p1);
            sum2 += __uint_as_float(p2) + __uint_as_float(p3);
            const int cw = nt * 8 + 2 * g;
            *(uint2*)&sm[P_OFF + rl1 * PSTR + cw] = make_uint2(p0, p1);
            *(uint2*)&sm[P_OFF + rl2 * PSTR + cw] = make_uint2(p2, p3);
        }
        sum1 += __shfl_xor_sync(0xffffffffu, sum1, 1);
        sum1 += __shfl_xor_sync(0xffffffffu, sum1, 2);
        sum2 += __shfl_xor_sync(0xffffffffu, sum2, 1);
        sum2 += __shfl_xor_sync(0xffffffffu, sum2, 2);
        l1 = l1 * a1 + sum1;
        l2 = l2 * a2 + sum2;

        // rescale O accumulators
        #pragma unroll
        for (int nt = 0; nt < 8; nt++) {
            o[nt][0] *= a1; o[nt][1] *= a1;
            o[nt][2] *= a2; o[nt][3] *= a2;
        }

        __syncwarp();   // P stores visible within the warp

        // ---- MMA2: O += P . V  (per warp: own 16 rows of P) ----
        #pragma unroll
        for (int ks = 0; ks < 8; ks++) {
            uint32_t pa[4];
            const int cb = ks * 8 + g;
            pa[0] = sm[P_OFF + rl1 * PSTR + cb];
            pa[1] = sm[P_OFF + rl2 * PSTR + cb];
            pa[2] = sm[P_OFF + rl1 * PSTR + cb + 4];
            pa[3] = sm[P_OFF + rl2 * PSTR + cb + 4];
            #pragma unroll
            for (int nt = 0; nt < 8; nt++) {
                const uint32_t b0 = sm[V_OFF + (ks * 8 + g) * VSTR + nt * 8 + r1];
                const uint32_t b1 = sm[V_OFF + (ks * 8 + g + 4) * VSTR + nt * 8 + r1];
                mma8(o[nt], pa, b0, b1);
            }
        }
        __syncwarp();   // MMA2's P reads done before next iter's P stores
    }

    // ---- epilogue ----
    const float i1 = 1.f / l1;
    const float i2 = 1.f / l2;
    float* dst1 = Og + base + (size_t)(q0 + rl1) * HD;
    float* dst2 = Og + base + (size_t)(q0 + rl2) * HD;
    #pragma unroll
    for (int nt = 0; nt < 8; nt++) {
        const int cw = nt * 8 + 2 * g;
        *(float2*)(dst1 + cw) = make_float2(o[nt][0] * i1, o[nt][1] * i1);
        *(float2*)(dst2 + cw) = make_float2(o[nt][2] * i2, o[nt][3] * i2);
    }
}

extern "C" void kernel_launch(void* const* d_in, const int* in_sizes, int n_in,
                              void* d_out, int out_size) {
    const float* Q = (const float*)d_in[0];
    const float* K = (const float*)d_in[1];
    const float* V = (const float*)d_in[2];
    float* O = (float*)d_out;

    const int BH = in_sizes[0] / (S_LEN * HD);   // 32

    cudaFuncSetAttribute(swa_mma_tf32,
                         cudaFuncAttributeMaxDynamicSharedMemorySize, SMEM_BYTES);

    dim3 grid(S_LEN / QT, BH);
    swa_mma_tf32<<<grid, 128, SMEM_BYTES>>>(Q, K, V, O);
}